// round 12
// baseline (speedup 1.0000x reference)
#include <cuda_runtime.h>
#include <cstdint>

#define NQ 32
#define NS 25
#define NL 64
#define NF 256
#define NH 64
#define NT (NQ * NS * 2)     // 1600 (q, s, i-half) tiles
#define XSP 260              // proj xs row stride (pad 4)
#define ATS 36               // attT row stride (mult of 4: float4-aligned)

// Scratch (allocation-free rule: __device__ globals)
__device__ float g_WqT[NQ * NH * NL];  // per q: [h][i]
__device__ float g_WhT[NS * NH * NL];  // per s: [h][j]
__device__ unsigned g_ticket;

typedef unsigned long long u64;

__device__ __forceinline__ float fast_ex2(float x) {
    float r; asm("ex2.approx.f32 %0, %1;" : "=f"(r) : "f"(x)); return r;
}
__device__ __forceinline__ float fast_rcp(float x) {
    float r; asm("rcp.approx.f32 %0, %1;" : "=f"(r) : "f"(x)); return r;
}
__device__ __forceinline__ float fast_tanh(float x) {
    float r; asm("tanh.approx.f32 %0, %1;" : "=f"(r) : "f"(x)); return r;
}
__device__ __forceinline__ u64 f2fma(u64 a, u64 b, u64 c) {
    u64 r; asm("fma.rn.f32x2 %0, %1, %2, %3;" : "=l"(r) : "l"(a), "l"(b), "l"(c)); return r;
}
__device__ __forceinline__ u64 dup2(float x) {
    u64 r; asm("mov.b64 %0, {%1, %1};" : "=l"(r) : "f"(x)); return r;
}

#define LOG2E 1.4426950408889634f

// K1: projection (+ ticket reset). One block per (sequence b, l-quarter).
__global__ __launch_bounds__(256) void k_project(const float* __restrict__ qs,
                                                 const float* __restrict__ hs,
                                                 const float* __restrict__ W,
                                                 const float* __restrict__ bias) {
    __shared__ float xs[16 * XSP];
    const int b  = blockIdx.x >> 2;
    const int lq = blockIdx.x & 3;
    const int t  = threadIdx.x;

    if (blockIdx.x == 0 && t == 0) g_ticket = 0u;  // visible to k_attn (kernel order)

    const float* x = ((b < NQ) ? (qs + (size_t)b * NL * NF)
                               : (hs + (size_t)(b - NQ) * NL * NF))
                     + (size_t)lq * 16 * NF;
    float* dst = (b < NQ) ? (g_WqT + (size_t)b * NH * NL)
                          : (g_WhT + (size_t)(b - NQ) * NH * NL);

    for (int e = t; e < 16 * NF / 4; e += 256) {
        int row = e >> 6;
        int c4 = (e & 63) * 4;
        *reinterpret_cast<float4*>(&xs[row * XSP + c4]) =
            *reinterpret_cast<const float4*>(&x[row * NF + c4]);
    }
    __syncthreads();

    const int h0 = 4 * (t >> 4);
    const int lr = t & 15;
    float acc[4] = {0.f, 0.f, 0.f, 0.f};

    #pragma unroll 2
    for (int f = 0; f < NF; f += 4) {
        float4 xv = *reinterpret_cast<const float4*>(&xs[lr * XSP + f]);
        #pragma unroll
        for (int c = 0; c < 4; c++) {
            float4 w = __ldg(reinterpret_cast<const float4*>(&W[(size_t)(h0 + c) * NF + f]));
            acc[c] = fmaf(w.x, xv.x, fmaf(w.y, xv.y, fmaf(w.z, xv.z, fmaf(w.w, xv.w, acc[c]))));
        }
    }
    const int l = lq * 16 + lr;
    #pragma unroll
    for (int c = 0; c < 4; c++)
        dst[(h0 + c) * NL + l] = acc[c] + __ldg(&bias[h0 + c]);
}

// K2: persistent software-pipelined kernel over 1600 (q, s, i-half) tiles.
// Iteration n: scores(tile n) fused at instruction level with AV(tile n-1).
// smem (floats): wqh[0..2048)=[NH][32]; whT[2048..6144)=[NH][64];
//   attT buffers: [6144..8448) and [8448..10752), each [64 j][ATS];
//   ticket slot [10752]. Total 10756 f = 43024 B -> occ 4.
__global__ __launch_bounds__(256, 4) void k_attn(const float* __restrict__ hs,
                                                 float* __restrict__ out) {
    extern __shared__ float sm[];
    float* wqh = sm;             // [NH][32]
    float* whT = sm + 2048;      // [NH][64]
    float* att0 = sm + 6144;     // [64][ATS]
    float* att1 = sm + 8448;     // [64][ATS]
    float* tslot = sm + 10752;

    const int t = threadIdx.x;

    // A-tiling indices
    const int i0a = 2 * (t >> 4);   // local query row in [0,32)
    const int j0 = 4 * (t & 15);    // support col in [0,64)
    // C-tiling indices
    const int ib = 4 * (t >> 5);    // warp-uniform local i-rows [0,32)
    const int fb = 4 * (t & 31);    // f cols [0,128) per pass

    if (t == 0) tslot[0] = __uint_as_float(atomicAdd(&g_ticket, 1u));
    __syncthreads();
    unsigned T = __float_as_uint(tslot[0]);

    int prevQ = 0, prevS = 0, prevHalf = 0;
    bool haveC = false;
    int buf = 0;

    for (;;) {
        const bool haveA = (T < NT);
        if (!haveA && !haveC) return;

        int q = 0, s = 0, half = 0;
        if (haveA) {
            q = (int)T / (2 * NS);
            int sb = (int)T % (2 * NS);
            s = sb >> 1;
            half = sb & 1;
            const float4* bsrc = reinterpret_cast<const float4*>(g_WhT + (size_t)s * NH * NL);
            float4* w2 = reinterpret_cast<float4*>(whT);
            for (int e = t; e < NH * NL / 4; e += 256) w2[e] = bsrc[e];
            const float* aq = g_WqT + (size_t)q * NH * NL + half * 32;
            for (int e = t; e < NH * 32 / 4; e += 256) {
                int h = e >> 3;
                int ii = (e & 7) * 4;
                *reinterpret_cast<float4*>(&wqh[h * 32 + ii]) =
                    *reinterpret_cast<const float4*>(&aq[h * NL + ii]);
            }
        }
        __syncthreads();   // wq/wh staged; attR (written before prev end-sync) visible

        float* attW = buf ? att1 : att0;   // A writes (tile T)
        float* attR = buf ? att0 : att1;   // C reads (tile T-1)

        float acc[2][4];
        #pragma unroll
        for (int r = 0; r < 2; r++)
            #pragma unroll
            for (int c = 0; c < 4; c++) acc[r][c] = 0.f;

        const float* hp = hs + (size_t)prevS * NL * NF + fb;
        float* op = out + (size_t)((prevQ * NS + prevS) * NL + prevHalf * 32 + ib) * NF + fb;

        u64 o[4][2];
        #pragma unroll
        for (int r = 0; r < 4; r++) { o[r][0] = 0ull; o[r][1] = 0ull; }

        // -------- fused sub-loop 0: A h=0..31, C f-pass 0 (j = 2h, 2h+1) --------
        #pragma unroll 2
        for (int h = 0; h < 32; h++) {
            if (haveA) {
                float2 a2 = *reinterpret_cast<const float2*>(&wqh[h * 32 + i0a]);
                float4 b4 = *reinterpret_cast<const float4*>(&whT[h * NL + j0]);
                acc[0][0] += fast_tanh(a2.x * b4.x);
                acc[0][1] += fast_tanh(a2.x * b4.y);
                acc[0][2] += fast_tanh(a2.x * b4.z);
                acc[0][3] += fast_tanh(a2.x * b4.w);
                acc[1][0] += fast_tanh(a2.y * b4.x);
                acc[1][1] += fast_tanh(a2.y * b4.y);
                acc[1][2] += fast_tanh(a2.y * b4.z);
                acc[1][3] += fast_tanh(a2.y * b4.w);
            }
            if (haveC) {
                #pragma unroll
                for (int u = 0; u < 2; u++) {
                    int j = 2 * h + u;
                    float4 a4 = *reinterpret_cast<const float4*>(&attR[j * ATS + ib]);
                    ulonglong2 hv = __ldg(reinterpret_cast<const ulonglong2*>(hp + (size_t)j * NF));
                    o[0][0] = f2fma(dup2(a4.x), hv.x, o[0][0]);
                    o[0][1] = f2fma(dup2(a4.x), hv.y, o[0][1]);
                    o[1][0] = f2fma(dup2(a4.y), hv.x, o[1][0]);
                    o[1][1] = f2fma(dup2(a4.y), hv.y, o[1][1]);
                    o[2][0] = f2fma(dup2(a4.z), hv.x, o[2][0]);
                    o[2][1] = f2fma(dup2(a4.z), hv.y, o[2][1]);
                    o[3][0] = f2fma(dup2(a4.w), hv.x, o[3][0]);
                    o[3][1] = f2fma(dup2(a4.w), hv.y, o[3][1]);
                }
            }
        }
        if (haveC) {   // store f-pass 0, reset accumulators
            #pragma unroll
            for (int r = 0; r < 4; r++) {
                ulonglong2 v; v.x = o[r][0]; v.y = o[r][1];
                *reinterpret_cast<ulonglong2*>(op + (size_t)r * NF) = v;
                o[r][0] = 0ull; o[r][1] = 0ull;
            }
        }

        // -------- fused sub-loop 1: A h=32..63, C f-pass 1 (j = 2h', 2h'+1) --------
        #pragma unroll 2
        for (int h = 32; h < 64; h++) {
            if (haveA) {
                float2 a2 = *reinterpret_cast<const float2*>(&wqh[h * 32 + i0a]);
                float4 b4 = *reinterpret_cast<const float4*>(&whT[h * NL + j0]);
                acc[0][0] += fast_tanh(a2.x * b4.x);
                acc[0][1] += fast_tanh(a2.x * b4.y);
                acc[0][2] += fast_tanh(a2.x * b4.z);
                acc[0][3] += fast_tanh(a2.x * b4.w);
                acc[1][0] += fast_tanh(a2.y * b4.x);
                acc[1][1] += fast_tanh(a2.y * b4.y);
                acc[1][2] += fast_tanh(a2.y * b4.z);
                acc[1][3] += fast_tanh(a2.y * b4.w);
            }
            if (haveC) {
                #pragma unroll
                for (int u = 0; u < 2; u++) {
                    int j = 2 * (h - 32) + u;
                    float4 a4 = *reinterpret_cast<const float4*>(&attR[j * ATS + ib]);
                    ulonglong2 hv = __ldg(reinterpret_cast<const ulonglong2*>(hp + 128 + (size_t)j * NF));
                    o[0][0] = f2fma(dup2(a4.x), hv.x, o[0][0]);
                    o[0][1] = f2fma(dup2(a4.x), hv.y, o[0][1]);
                    o[1][0] = f2fma(dup2(a4.y), hv.x, o[1][0]);
                    o[1][1] = f2fma(dup2(a4.y), hv.y, o[1][1]);
                    o[2][0] = f2fma(dup2(a4.z), hv.x, o[2][0]);
                    o[2][1] = f2fma(dup2(a4.z), hv.y, o[2][1]);
                    o[3][0] = f2fma(dup2(a4.w), hv.x, o[3][0]);
                    o[3][1] = f2fma(dup2(a4.w), hv.y, o[3][1]);
                }
            }
        }
        if (haveC) {   // store f-pass 1
            #pragma unroll
            for (int r = 0; r < 4; r++) {
                ulonglong2 v; v.x = o[r][0]; v.y = o[r][1];
                *reinterpret_cast<ulonglong2*>(op + 128 + (size_t)r * NF) = v;
            }
        }

        if (haveA) {
            // softmax over j per row (64 j of a row live in one 16-lane group)
            #pragma unroll
            for (int r = 0; r < 2; r++) {
                float m = fmaxf(fmaxf(acc[r][0], acc[r][1]), fmaxf(acc[r][2], acc[r][3]));
                #pragma unroll
                for (int d = 1; d < 16; d <<= 1)
                    m = fmaxf(m, __shfl_xor_sync(0xffffffffu, m, d));
                float e0 = fast_ex2((acc[r][0] - m) * LOG2E);
                float e1 = fast_ex2((acc[r][1] - m) * LOG2E);
                float e2 = fast_ex2((acc[r][2] - m) * LOG2E);
                float e3 = fast_ex2((acc[r][3] - m) * LOG2E);
                float ssum = (e0 + e1) + (e2 + e3);
                #pragma unroll
                for (int d = 1; d < 16; d <<= 1)
                    ssum += __shfl_xor_sync(0xffffffffu, ssum, d);
                float inv = fast_rcp(ssum);
                attW[(j0 + 0) * ATS + i0a + r] = e0 * inv;
                attW[(j0 + 1) * ATS + i0a + r] = e1 * inv;
                attW[(j0 + 2) * ATS + i0a + r] = e2 * inv;
                attW[(j0 + 3) * ATS + i0a + r] = e3 * inv;
            }
        }

        if (t == 0) tslot[0] = __uint_as_float(atomicAdd(&g_ticket, 1u));
        __syncthreads();   // attW visible; tslot visible; all smem reads of this iter done

        prevQ = q; prevS = s; prevHalf = half;
        haveC = haveA;
        T = __float_as_uint(tslot[0]);
        buf ^= 1;
    }
}

extern "C" void kernel_launch(void* const* d_in, const int* in_sizes, int n_in,
                              void* d_out, int out_size) {
    const float* qs = (const float*)d_in[0];
    const float* hs = (const float*)d_in[1];
    const float* W  = (const float*)d_in[2];
    const float* b  = (const float*)d_in[3];
    float* out = (float*)d_out;

    const int smem_attn = 10756 * (int)sizeof(float);  // 43024 B -> occ 4
    cudaFuncSetAttribute(k_attn, cudaFuncAttributeMaxDynamicSharedMemorySize, smem_attn);

    k_project<<<(NQ + NS) * 4, 256>>>(qs, hs, W, b);
    k_attn<<<148 * 4, 256, smem_attn>>>(hs, out);
}

// round 13
// speedup vs baseline: 1.9028x; 1.9028x over previous
#include <cuda_runtime.h>
#include <cstdint>

#define NQ 32
#define NS 25
#define NL 64
#define NF 256
#define NH 64
#define NT (NQ * NS)         // 800 (q, s) tiles
#define XSP 260              // proj xs row stride (pad 4)
#define ATS 68               // att row stride (banks: 4*gid+tig, conflict-free frags)
#define HSS 72               // hsq row stride (banks: 8*tig+gid, conflict-free frags)

// Scratch (allocation-free rule: __device__ globals)
__device__ float g_WqT[NQ * NH * NL];    // per q: [h][i]
__device__ float g_WhT[NS * NH * NL];    // per s: [h][j]
__device__ float g_hsT32[NS * NL * NF];  // hs pre-rounded to tf32
__device__ unsigned g_ticket;

__device__ __forceinline__ float fast_ex2(float x) {
    float r; asm("ex2.approx.f32 %0, %1;" : "=f"(r) : "f"(x)); return r;
}
__device__ __forceinline__ float fast_rcp(float x) {
    float r; asm("rcp.approx.f32 %0, %1;" : "=f"(r) : "f"(x)); return r;
}
__device__ __forceinline__ float fast_tanh(float x) {
    float r; asm("tanh.approx.f32 %0, %1;" : "=f"(r) : "f"(x)); return r;
}
__device__ __forceinline__ unsigned cvt_tf32(float x) {
    unsigned r; asm("cvt.rna.tf32.f32 %0, %1;" : "=r"(r) : "f"(x)); return r;
}
// D(16x8,f32) += A(16x8,tf32,row) * B(8x8,tf32,col)
__device__ __forceinline__ void mma_tf32(float* d,
                                         unsigned a0, unsigned a1, unsigned a2, unsigned a3,
                                         unsigned b0, unsigned b1) {
    asm volatile(
        "mma.sync.aligned.m16n8k8.row.col.f32.tf32.tf32.f32 "
        "{%0,%1,%2,%3}, {%4,%5,%6,%7}, {%8,%9}, {%0,%1,%2,%3};"
        : "+f"(d[0]), "+f"(d[1]), "+f"(d[2]), "+f"(d[3])
        : "r"(a0), "r"(a1), "r"(a2), "r"(a3), "r"(b0), "r"(b1));
}

#define LOG2E 1.4426950408889634f

// K1: projection (+ ticket reset + hs->tf32 pre-round).
__global__ __launch_bounds__(256) void k_project(const float* __restrict__ qs,
                                                 const float* __restrict__ hs,
                                                 const float* __restrict__ W,
                                                 const float* __restrict__ bias) {
    __shared__ float xs[16 * XSP];
    const int b  = blockIdx.x >> 2;
    const int lq = blockIdx.x & 3;
    const int t  = threadIdx.x;

    if (blockIdx.x == 0 && t == 0) g_ticket = 0u;

    // hs -> tf32 (grid-stride; independent of the projection below)
    for (int e = blockIdx.x * 256 + t; e < NS * NL * NF; e += gridDim.x * 256)
        g_hsT32[e] = __uint_as_float(cvt_tf32(__ldg(&hs[e])));

    const float* x = ((b < NQ) ? (qs + (size_t)b * NL * NF)
                               : (hs + (size_t)(b - NQ) * NL * NF))
                     + (size_t)lq * 16 * NF;
    float* dst = (b < NQ) ? (g_WqT + (size_t)b * NH * NL)
                          : (g_WhT + (size_t)(b - NQ) * NH * NL);

    for (int e = t; e < 16 * NF / 4; e += 256) {
        int row = e >> 6;
        int c4 = (e & 63) * 4;
        *reinterpret_cast<float4*>(&xs[row * XSP + c4]) =
            *reinterpret_cast<const float4*>(&x[row * NF + c4]);
    }
    __syncthreads();

    const int h0 = 4 * (t >> 4);
    const int lr = t & 15;
    float acc[4] = {0.f, 0.f, 0.f, 0.f};

    #pragma unroll 2
    for (int f = 0; f < NF; f += 4) {
        float4 xv = *reinterpret_cast<const float4*>(&xs[lr * XSP + f]);
        #pragma unroll
        for (int c = 0; c < 4; c++) {
            float4 w = __ldg(reinterpret_cast<const float4*>(&W[(size_t)(h0 + c) * NF + f]));
            acc[c] = fmaf(w.x, xv.x, fmaf(w.y, xv.y, fmaf(w.z, xv.z, fmaf(w.w, xv.w, acc[c]))));
        }
    }
    const int l = lq * 16 + lr;
    #pragma unroll
    for (int c = 0; c < 4; c++)
        dst[(h0 + c) * NL + l] = acc[c] + __ldg(&bias[h0 + c]);
}

// K2: persistent fused kernel, 800 (q,s) tiles; phase C on tensor cores.
// smem (floats): phase A: wqT[0..4096)=[64h][64i]; whT[4096..8192)
//   overlay: attH[0..4352)=[64i][ATS]; attL[4352..8704); hsq[8704..13312)=[64j][HSS]
//   ticket [13312]. Total 13316 f = 53264 B -> occ 4.
__global__ __launch_bounds__(256, 4) void k_attn(float* __restrict__ out) {
    extern __shared__ float sm[];
    float* wqT = sm;
    float* whT = sm + 4096;
    float* attH = sm;            // overlay: att hi (tf32-rounded), [i][j] stride ATS
    float* attL = sm + 4352;     // att lo residual
    float* hsq  = sm + 8704;     // staged hs tf32, [j][64f-chunk] stride HSS
    float* tslot = sm + 13312;

    const int t = threadIdx.x;
    const int lane = t & 31, w = t >> 5;
    const int gid = lane >> 2, tig = lane & 3;
    const int i0 = 4 * (t >> 4), j0 = 4 * (t & 15);   // phase A tiling
    const int m0 = 16 * (w & 3), nw = 32 * (w >> 2);  // phase C warp tiling

    for (;;) {
        if (t == 0) tslot[0] = __uint_as_float(atomicAdd(&g_ticket, 1u));
        __syncthreads();   // also: last pass's smem reads done before wqT overwrite
        const unsigned T = __float_as_uint(tslot[0]);
        if (T >= NT) return;
        const int q = (int)T / NS;
        const int s = (int)T % NS;

        {
            const float4* a4 = reinterpret_cast<const float4*>(g_WqT + (size_t)q * NH * NL);
            const float4* b4 = reinterpret_cast<const float4*>(g_WhT + (size_t)s * NH * NL);
            float4* w1 = reinterpret_cast<float4*>(wqT);
            float4* w2 = reinterpret_cast<float4*>(whT);
            for (int e = t; e < NH * NL / 4; e += 256) { w1[e] = a4[e]; w2[e] = b4[e]; }
        }
        __syncthreads();

        // Phase A: acc[r][c] = sum_h tanh(wq[i0+r][h] * wh[j0+c][h])
        float acc[4][4];
        #pragma unroll
        for (int r = 0; r < 4; r++)
            #pragma unroll
            for (int c = 0; c < 4; c++) acc[r][c] = 0.f;

        #pragma unroll 2
        for (int h = 0; h < NH; h++) {
            float4 a4 = *reinterpret_cast<const float4*>(&wqT[h * NL + i0]);
            float4 b4 = *reinterpret_cast<const float4*>(&whT[h * NL + j0]);
            float av[4] = {a4.x, a4.y, a4.z, a4.w};
            float bv[4] = {b4.x, b4.y, b4.z, b4.w};
            #pragma unroll
            for (int r = 0; r < 4; r++)
                #pragma unroll
                for (int c = 0; c < 4; c++)
                    acc[r][c] += fast_tanh(av[r] * bv[c]);
        }

        // Phase B: softmax over j per row.
        float inv[4];
        #pragma unroll
        for (int r = 0; r < 4; r++) {
            float m = fmaxf(fmaxf(acc[r][0], acc[r][1]), fmaxf(acc[r][2], acc[r][3]));
            #pragma unroll
            for (int d = 1; d < 16; d <<= 1)
                m = fmaxf(m, __shfl_xor_sync(0xffffffffu, m, d));
            float e0 = fast_ex2((acc[r][0] - m) * LOG2E);
            float e1 = fast_ex2((acc[r][1] - m) * LOG2E);
            float e2 = fast_ex2((acc[r][2] - m) * LOG2E);
            float e3 = fast_ex2((acc[r][3] - m) * LOG2E);
            acc[r][0] = e0; acc[r][1] = e1; acc[r][2] = e2; acc[r][3] = e3;
            float ssum = (e0 + e1) + (e2 + e3);
            #pragma unroll
            for (int d = 1; d < 16; d <<= 1)
                ssum += __shfl_xor_sync(0xffffffffu, ssum, d);
            inv[r] = fast_rcp(ssum);
        }

        __syncthreads();  // all phase-A smem reads complete before overlay writes

        // Store att split to tf32 hi + residual lo, row-major [i][j].
        #pragma unroll
        for (int r = 0; r < 4; r++) {
            float vh[4], vl[4];
            #pragma unroll
            for (int c = 0; c < 4; c++) {
                float v = acc[r][c] * inv[r];
                unsigned hb = cvt_tf32(v);
                vh[c] = __uint_as_float(hb);
                vl[c] = __uint_as_float(cvt_tf32(v - vh[c]));
            }
            *reinterpret_cast<float4*>(&attH[(i0 + r) * ATS + j0]) =
                make_float4(vh[0], vh[1], vh[2], vh[3]);
            *reinterpret_cast<float4*>(&attL[(i0 + r) * ATS + j0]) =
                make_float4(vl[0], vl[1], vl[2], vl[3]);
        }
        // (no sync needed here: pass-0's post-staging sync orders these stores)

        // Phase C (tensor): out[i][f] = sum_j att[i][j] * hs_t32[j][f].
        // 4 f-passes of 64; warp w: m-tile m0 (16 rows), n-offset nw (32 f -> 4 n-tiles).
        const float* hbase = g_hsT32 + (size_t)s * NL * NF;
        float* ob = out + (size_t)((q * NS + s) * NL) * NF;

        #pragma unroll
        for (int p = 0; p < 4; p++) {
            for (int e = t; e < NL * 64 / 4; e += 256) {
                int j = e >> 4;
                int f4 = (e & 15) * 4;
                *reinterpret_cast<float4*>(&hsq[j * HSS + f4]) =
                    __ldg(reinterpret_cast<const float4*>(&hbase[(size_t)j * NF + 64 * p + f4]));
            }
            __syncthreads();   // hsq staged; att stores (p==0) visible

            float d[4][4];
            #pragma unroll
            for (int nt = 0; nt < 4; nt++)
                #pragma unroll
                for (int e = 0; e < 4; e++) d[nt][e] = 0.f;

            const float* aH = attH + (size_t)(m0 + gid) * ATS;
            const float* aL = attL + (size_t)(m0 + gid) * ATS;

            #pragma unroll
            for (int k0 = 0; k0 < NL; k0 += 8) {
                unsigned ah0 = __float_as_uint(aH[k0 + tig]);
                unsigned ah1 = __float_as_uint(aH[8 * ATS + k0 + tig]);
                unsigned ah2 = __float_as_uint(aH[k0 + tig + 4]);
                unsigned ah3 = __float_as_uint(aH[8 * ATS + k0 + tig + 4]);
                unsigned al0 = __float_as_uint(aL[k0 + tig]);
                unsigned al1 = __float_as_uint(aL[8 * ATS + k0 + tig]);
                unsigned al2 = __float_as_uint(aL[k0 + tig + 4]);
                unsigned al3 = __float_as_uint(aL[8 * ATS + k0 + tig + 4]);
                const float* hr0 = hsq + (size_t)(k0 + tig) * HSS + nw + gid;
                const float* hr1 = hsq + (size_t)(k0 + tig + 4) * HSS + nw + gid;
                #pragma unroll
                for (int nt = 0; nt < 4; nt++) {
                    unsigned b0 = __float_as_uint(hr0[8 * nt]);
                    unsigned b1 = __float_as_uint(hr1[8 * nt]);
                    mma_tf32(d[nt], ah0, ah1, ah2, ah3, b0, b1);
                    mma_tf32(d[nt], al0, al1, al2, al3, b0, b1);
                }
            }

            #pragma unroll
            for (int nt = 0; nt < 4; nt++) {
                int col = 64 * p + nw + 8 * nt + 2 * tig;
                *reinterpret_cast<float2*>(&ob[(size_t)(m0 + gid) * NF + col]) =
                    make_float2(d[nt][0], d[nt][1]);
                *reinterpret_cast<float2*>(&ob[(size_t)(m0 + gid + 8) * NF + col]) =
                    make_float2(d[nt][2], d[nt][3]);
            }
            __syncthreads();   // frag reads done before next hsq overwrite
        }
    }
}

extern "C" void kernel_launch(void* const* d_in, const int* in_sizes, int n_in,
                              void* d_out, int out_size) {
    const float* qs = (const float*)d_in[0];
    const float* hs = (const float*)d_in[1];
    const float* W  = (const float*)d_in[2];
    const float* b  = (const float*)d_in[3];
    float* out = (float*)d_out;

    const int smem_attn = 13316 * (int)sizeof(float);  // 53264 B -> occ 4
    cudaFuncSetAttribute(k_attn, cudaFuncAttributeMaxDynamicSharedMemorySize, smem_attn);

    k_project<<<(NQ + NS) * 4, 256>>>(qs, hs, W, b);
    k_attn<<<148 * 4, 256, smem_attn>>>(out);
}

// round 14
// speedup vs baseline: 1.9421x; 1.0207x over previous
#include <cuda_runtime.h>
#include <cstdint>

#define NQ 32
#define NS 25
#define NL 64
#define NF 256
#define NH 64
#define NT (NQ * NS)         // 800 (q, s) tiles
#define XSP 260              // proj xs row stride (pad 4)
#define ATS 68               // att row stride (banks 4*gid+tig: conflict-free frags)
#define HSS 72               // hsq row stride (banks 8*tig+gid: conflict-free frags)

// Scratch (allocation-free rule: __device__ globals)
__device__ float g_WqT[NQ * NH * NL];    // per q: [h][i]
__device__ float g_WhT[NS * NH * NL];    // per s: [h][j]
__device__ float g_hsT32[NS * NL * NF];  // hs pre-rounded to tf32
__device__ unsigned g_ticket;

__device__ __forceinline__ float fast_ex2(float x) {
    float r; asm("ex2.approx.f32 %0, %1;" : "=f"(r) : "f"(x)); return r;
}
__device__ __forceinline__ float fast_rcp(float x) {
    float r; asm("rcp.approx.f32 %0, %1;" : "=f"(r) : "f"(x)); return r;
}
__device__ __forceinline__ float fast_tanh(float x) {
    float r; asm("tanh.approx.f32 %0, %1;" : "=f"(r) : "f"(x)); return r;
}
__device__ __forceinline__ unsigned cvt_tf32(float x) {
    unsigned r; asm("cvt.rna.tf32.f32 %0, %1;" : "=r"(r) : "f"(x)); return r;
}
// D(16x8,f32) += A(16x8,tf32,row) * B(8x8,tf32,col)
__device__ __forceinline__ void mma_tf32(float* d,
                                         unsigned a0, unsigned a1, unsigned a2, unsigned a3,
                                         unsigned b0, unsigned b1) {
    asm volatile(
        "mma.sync.aligned.m16n8k8.row.col.f32.tf32.tf32.f32 "
        "{%0,%1,%2,%3}, {%4,%5,%6,%7}, {%8,%9}, {%0,%1,%2,%3};"
        : "+f"(d[0]), "+f"(d[1]), "+f"(d[2]), "+f"(d[3])
        : "r"(a0), "r"(a1), "r"(a2), "r"(a3), "r"(b0), "r"(b1));
}

#define LOG2E 1.4426950408889634f

// K1: projection (+ ticket reset + hs->tf32 pre-round).
__global__ __launch_bounds__(256) void k_project(const float* __restrict__ qs,
                                                 const float* __restrict__ hs,
                                                 const float* __restrict__ W,
                                                 const float* __restrict__ bias) {
    __shared__ float xs[16 * XSP];
    const int b  = blockIdx.x >> 2;
    const int lq = blockIdx.x & 3;
    const int t  = threadIdx.x;

    if (blockIdx.x == 0 && t == 0) g_ticket = 0u;

    // hs -> tf32 (grid-stride; independent of the projection below)
    for (int e = blockIdx.x * 256 + t; e < NS * NL * NF; e += gridDim.x * 256)
        g_hsT32[e] = __uint_as_float(cvt_tf32(__ldg(&hs[e])));

    const float* x = ((b < NQ) ? (qs + (size_t)b * NL * NF)
                               : (hs + (size_t)(b - NQ) * NL * NF))
                     + (size_t)lq * 16 * NF;
    float* dst = (b < NQ) ? (g_WqT + (size_t)b * NH * NL)
                          : (g_WhT + (size_t)(b - NQ) * NH * NL);

    for (int e = t; e < 16 * NF / 4; e += 256) {
        int row = e >> 6;
        int c4 = (e & 63) * 4;
        *reinterpret_cast<float4*>(&xs[row * XSP + c4]) =
            *reinterpret_cast<const float4*>(&x[row * NF + c4]);
    }
    __syncthreads();

    const int h0 = 4 * (t >> 4);
    const int lr = t & 15;
    float acc[4] = {0.f, 0.f, 0.f, 0.f};

    #pragma unroll 2
    for (int f = 0; f < NF; f += 4) {
        float4 xv = *reinterpret_cast<const float4*>(&xs[lr * XSP + f]);
        #pragma unroll
        for (int c = 0; c < 4; c++) {
            float4 w = __ldg(reinterpret_cast<const float4*>(&W[(size_t)(h0 + c) * NF + f]));
            acc[c] = fmaf(w.x, xv.x, fmaf(w.y, xv.y, fmaf(w.z, xv.z, fmaf(w.w, xv.w, acc[c]))));
        }
    }
    const int l = lq * 16 + lr;
    #pragma unroll
    for (int c = 0; c < 4; c++)
        dst[(h0 + c) * NL + l] = acc[c] + __ldg(&bias[h0 + c]);
}

// K2: persistent fused kernel, 800 (q,s) tiles; phase C on tensor cores (tf32).
// smem (floats): phase A: wqT[0..4096)=[64h][64i]; whT[4096..8192)=[64h][64j]
//   overlay: attH[0..4352)=[64i][ATS] (tf32-rounded); hsq[4352..8960)=[64j][HSS]
//   ticket [8960]. Total 8964 f = 35856 B -> occ 4 (regs-bound).
// Odd CTAs take a one-time ~10K-cycle entry stagger so co-resident CTAs run
// phase-shifted: one CTA's MUFU-bound A overlaps another's tensor/LDS-bound C.
__global__ __launch_bounds__(256, 4) void k_attn(float* __restrict__ out) {
    extern __shared__ float sm[];
    float* wqT = sm;
    float* whT = sm + 4096;
    float* attH = sm;            // overlay: att (tf32-rounded), [i][j] stride ATS
    float* hsq  = sm + 4352;     // staged hs tf32, [j][64f-chunk] stride HSS
    float* tslot = sm + 8960;

    const int t = threadIdx.x;
    const int lane = t & 31, w = t >> 5;
    const int gid = lane >> 2, tig = lane & 3;
    const int i0 = 4 * (t >> 4), j0 = 4 * (t & 15);   // phase A tiling
    const int m0 = 16 * (w & 3), nw = 32 * (w >> 2);  // phase C warp tiling

    // de-lockstep: odd CTAs start ~half a tile late (timing-only; no output effect)
    if (blockIdx.x & 1) {
        long long st = clock64();
        while (clock64() - st < 10000) { }
    }

    for (;;) {
        if (t == 0) tslot[0] = __uint_as_float(atomicAdd(&g_ticket, 1u));
        __syncthreads();   // also: last pass's smem reads done before wqT overwrite
        const unsigned T = __float_as_uint(tslot[0]);
        if (T >= NT) return;
        const int q = (int)T / NS;
        const int s = (int)T % NS;

        {
            const float4* a4 = reinterpret_cast<const float4*>(g_WqT + (size_t)q * NH * NL);
            const float4* b4 = reinterpret_cast<const float4*>(g_WhT + (size_t)s * NH * NL);
            float4* w1 = reinterpret_cast<float4*>(wqT);
            float4* w2 = reinterpret_cast<float4*>(whT);
            for (int e = t; e < NH * NL / 4; e += 256) { w1[e] = a4[e]; w2[e] = b4[e]; }
        }
        __syncthreads();

        // Phase A: acc[r][c] = sum_h tanh(wq[i0+r][h] * wh[j0+c][h])
        float acc[4][4];
        #pragma unroll
        for (int r = 0; r < 4; r++)
            #pragma unroll
            for (int c = 0; c < 4; c++) acc[r][c] = 0.f;

        #pragma unroll 2
        for (int h = 0; h < NH; h++) {
            float4 a4 = *reinterpret_cast<const float4*>(&wqT[h * NL + i0]);
            float4 b4 = *reinterpret_cast<const float4*>(&whT[h * NL + j0]);
            float av[4] = {a4.x, a4.y, a4.z, a4.w};
            float bv[4] = {b4.x, b4.y, b4.z, b4.w};
            #pragma unroll
            for (int r = 0; r < 4; r++)
                #pragma unroll
                for (int c = 0; c < 4; c++)
                    acc[r][c] += fast_tanh(av[r] * bv[c]);
        }

        // Phase B: softmax over j per row.
        float inv[4];
        #pragma unroll
        for (int r = 0; r < 4; r++) {
            float m = fmaxf(fmaxf(acc[r][0], acc[r][1]), fmaxf(acc[r][2], acc[r][3]));
            #pragma unroll
            for (int d = 1; d < 16; d <<= 1)
                m = fmaxf(m, __shfl_xor_sync(0xffffffffu, m, d));
            float e0 = fast_ex2((acc[r][0] - m) * LOG2E);
            float e1 = fast_ex2((acc[r][1] - m) * LOG2E);
            float e2 = fast_ex2((acc[r][2] - m) * LOG2E);
            float e3 = fast_ex2((acc[r][3] - m) * LOG2E);
            acc[r][0] = e0; acc[r][1] = e1; acc[r][2] = e2; acc[r][3] = e3;
            float ssum = (e0 + e1) + (e2 + e3);
            #pragma unroll
            for (int d = 1; d < 16; d <<= 1)
                ssum += __shfl_xor_sync(0xffffffffu, ssum, d);
            inv[r] = fast_rcp(ssum);
        }

        __syncthreads();  // all phase-A smem reads complete before overlay writes

        // Store att tf32-rounded, row-major [i][j].
        #pragma unroll
        for (int r = 0; r < 4; r++) {
            float vh[4];
            #pragma unroll
            for (int c = 0; c < 4; c++)
                vh[c] = __uint_as_float(cvt_tf32(acc[r][c] * inv[r]));
            *reinterpret_cast<float4*>(&attH[(i0 + r) * ATS + j0]) =
                make_float4(vh[0], vh[1], vh[2], vh[3]);
        }
        // (pass-0's post-staging sync orders these stores)

        // Phase C (tensor): out[i][f] = sum_j att[i][j] * hs_t32[j][f].
        // 4 f-passes of 64; warp w: m-tile m0 (16 rows), n-offset nw (4 n-tiles of 8).
        const float* hbase = g_hsT32 + (size_t)s * NL * NF;
        float* ob = out + (size_t)((q * NS + s) * NL) * NF;

        #pragma unroll
        for (int p = 0; p < 4; p++) {
            for (int e = t; e < NL * 64 / 4; e += 256) {
                int j = e >> 4;
                int f4 = (e & 15) * 4;
                *reinterpret_cast<float4*>(&hsq[j * HSS + f4]) =
                    __ldg(reinterpret_cast<const float4*>(&hbase[(size_t)j * NF + 64 * p + f4]));
            }
            __syncthreads();   // hsq staged; att stores (p==0) visible

            float d[4][4];
            #pragma unroll
            for (int nt = 0; nt < 4; nt++)
                #pragma unroll
                for (int e = 0; e < 4; e++) d[nt][e] = 0.f;

            const float* aH = attH + (size_t)(m0 + gid) * ATS;

            #pragma unroll
            for (int k0 = 0; k0 < NL; k0 += 8) {
                unsigned ah0 = __float_as_uint(aH[k0 + tig]);
                unsigned ah1 = __float_as_uint(aH[8 * ATS + k0 + tig]);
                unsigned ah2 = __float_as_uint(aH[k0 + tig + 4]);
                unsigned ah3 = __float_as_uint(aH[8 * ATS + k0 + tig + 4]);
                const float* hr0 = hsq + (size_t)(k0 + tig) * HSS + nw + gid;
                const float* hr1 = hsq + (size_t)(k0 + tig + 4) * HSS + nw + gid;
                #pragma unroll
                for (int nt = 0; nt < 4; nt++) {
                    unsigned b0 = __float_as_uint(hr0[8 * nt]);
                    unsigned b1 = __float_as_uint(hr1[8 * nt]);
                    mma_tf32(d[nt], ah0, ah1, ah2, ah3, b0, b1);
                }
            }

            #pragma unroll
            for (int nt = 0; nt < 4; nt++) {
                int col = 64 * p + nw + 8 * nt + 2 * tig;
                *reinterpret_cast<float2*>(&ob[(size_t)(m0 + gid) * NF + col]) =
                    make_float2(d[nt][0], d[nt][1]);
                *reinterpret_cast<float2*>(&ob[(size_t)(m0 + gid + 8) * NF + col]) =
                    make_float2(d[nt][2], d[nt][3]);
            }
            __syncthreads();   // frag reads done before next hsq overwrite
        }
    }
}

extern "C" void kernel_launch(void* const* d_in, const int* in_sizes, int n_in,
                              void* d_out, int out_size) {
    const float* qs = (const float*)d_in[0];
    const float* hs = (const float*)d_in[1];
    const float* W  = (const float*)d_in[2];
    const float* b  = (const float*)d_in[3];
    float* out = (float*)d_out;

    const int smem_attn = 8964 * (int)sizeof(float);  // 35856 B -> occ 4
    cudaFuncSetAttribute(k_attn, cudaFuncAttributeMaxDynamicSharedMemorySize, smem_attn);

    k_project<<<(NQ + NS) * 4, 256>>>(qs, hs, W, b);
    k_attn<<<148 * 4, 256, smem_attn>>>(out);
}

// round 15
// speedup vs baseline: 1.9801x; 1.0196x over previous
#include <cuda_runtime.h>
#include <cstdint>

#define NQ 32
#define NS 25
#define NL 64
#define NF 256
#define NH 64
#define NT (NQ * NS)         // 800 (q, s) tiles
#define XSP 260              // proj xs row stride (pad 4)
#define ATS 68               // att row stride (banks 4*gid+tig: conflict-free frags)
#define HSS 72               // hsq row stride (banks 8*tig+gid: conflict-free frags)

// Scratch (allocation-free rule: __device__ globals)
__device__ float g_WqT[NQ * NH * NL];    // per q: [h][i]
__device__ float g_WhT[NS * NH * NL];    // per s: [h][j]
__device__ float g_hsT32[NS * NL * NF];  // hs pre-rounded to tf32
__device__ unsigned g_ticket;

__device__ __forceinline__ float fast_ex2(float x) {
    float r; asm("ex2.approx.f32 %0, %1;" : "=f"(r) : "f"(x)); return r;
}
__device__ __forceinline__ float fast_rcp(float x) {
    float r; asm("rcp.approx.f32 %0, %1;" : "=f"(r) : "f"(x)); return r;
}
__device__ __forceinline__ float fast_tanh(float x) {
    float r; asm("tanh.approx.f32 %0, %1;" : "=f"(r) : "f"(x)); return r;
}
__device__ __forceinline__ unsigned cvt_tf32(float x) {
    unsigned r; asm("cvt.rna.tf32.f32 %0, %1;" : "=r"(r) : "f"(x)); return r;
}
// D(16x8,f32) += A(16x8,tf32,row) * B(8x8,tf32,col)
__device__ __forceinline__ void mma_tf32(float* d,
                                         unsigned a0, unsigned a1, unsigned a2, unsigned a3,
                                         unsigned b0, unsigned b1) {
    asm volatile(
        "mma.sync.aligned.m16n8k8.row.col.f32.tf32.tf32.f32 "
        "{%0,%1,%2,%3}, {%4,%5,%6,%7}, {%8,%9}, {%0,%1,%2,%3};"
        : "+f"(d[0]), "+f"(d[1]), "+f"(d[2]), "+f"(d[3])
        : "r"(a0), "r"(a1), "r"(a2), "r"(a3), "r"(b0), "r"(b1));
}

#define LOG2E 1.4426950408889634f

// K1: projection (+ ticket reset + hs->tf32 pre-round).
__global__ __launch_bounds__(256) void k_project(const float* __restrict__ qs,
                                                 const float* __restrict__ hs,
                                                 const float* __restrict__ W,
                                                 const float* __restrict__ bias) {
    __shared__ float xs[16 * XSP];
    const int b  = blockIdx.x >> 2;
    const int lq = blockIdx.x & 3;
    const int t  = threadIdx.x;

    if (blockIdx.x == 0 && t == 0) g_ticket = 0u;

    // hs -> tf32 (grid-stride; independent of the projection below)
    for (int e = blockIdx.x * 256 + t; e < NS * NL * NF; e += gridDim.x * 256)
        g_hsT32[e] = __uint_as_float(cvt_tf32(__ldg(&hs[e])));

    const float* x = ((b < NQ) ? (qs + (size_t)b * NL * NF)
                               : (hs + (size_t)(b - NQ) * NL * NF))
                     + (size_t)lq * 16 * NF;
    float* dst = (b < NQ) ? (g_WqT + (size_t)b * NH * NL)
                          : (g_WhT + (size_t)(b - NQ) * NH * NL);

    for (int e = t; e < 16 * NF / 4; e += 256) {
        int row = e >> 6;
        int c4 = (e & 63) * 4;
        *reinterpret_cast<float4*>(&xs[row * XSP + c4]) =
            *reinterpret_cast<const float4*>(&x[row * NF + c4]);
    }
    __syncthreads();

    const int h0 = 4 * (t >> 4);
    const int lr = t & 15;
    float acc[4] = {0.f, 0.f, 0.f, 0.f};

    #pragma unroll 2
    for (int f = 0; f < NF; f += 4) {
        float4 xv = *reinterpret_cast<const float4*>(&xs[lr * XSP + f]);
        #pragma unroll
        for (int c = 0; c < 4; c++) {
            float4 w = __ldg(reinterpret_cast<const float4*>(&W[(size_t)(h0 + c) * NF + f]));
            acc[c] = fmaf(w.x, xv.x, fmaf(w.y, xv.y, fmaf(w.z, xv.z, fmaf(w.w, xv.w, acc[c]))));
        }
    }
    const int l = lq * 16 + lr;
    #pragma unroll
    for (int c = 0; c < 4; c++)
        dst[(h0 + c) * NL + l] = acc[c] + __ldg(&bias[h0 + c]);
}

// K2: persistent fused kernel, 800 (q,s) tiles; phase C on tensor cores (tf32)
// with double-buffered hs staging (1 sync per pass) + prefetched ticket.
// smem (floats): phase A: wqT[0..4096)=[64h][64i]; whT[4096..8192)=[64h][64j]
//   overlay: attH[0..4352)=[64i][ATS]; hsb0[4352..8960); hsb1[8960..13568)
//            (each [64j][HSS] = one 64-f tf32 chunk of hs[s])
//   ticket slot [13568]. Total 13572 f = 54288 B -> occ 4.
__global__ __launch_bounds__(256, 4) void k_attn(float* __restrict__ out) {
    extern __shared__ float sm[];
    float* wqT = sm;
    float* whT = sm + 4096;
    float* attH = sm;            // overlay: att (tf32-rounded), [i][j] stride ATS
    float* hsb0 = sm + 4352;
    float* hsb1 = sm + 8960;
    float* tslot = sm + 13568;

    const int t = threadIdx.x;
    const int lane = t & 31, w = t >> 5;
    const int gid = lane >> 2, tig = lane & 3;
    const int i0 = 4 * (t >> 4), j0 = 4 * (t & 15);   // phase A tiling
    const int m0 = 16 * (w & 3), nw = 32 * (w >> 2);  // phase C warp tiling

    // staging indices (same for every pass)
    const int sj = t >> 4;           // row j (16 lanes per row group... e>>4 with 4 iters)
    if (t == 0) tslot[0] = __uint_as_float(atomicAdd(&g_ticket, 1u));
    __syncthreads();

    for (;;) {
        const unsigned T = __float_as_uint(tslot[0]);   // published by prior pass-3 sync
        if (T >= NT) return;
        const int q = (int)T / NS;
        const int s = (int)T % NS;

        {
            const float4* a4 = reinterpret_cast<const float4*>(g_WqT + (size_t)q * NH * NL);
            const float4* b4 = reinterpret_cast<const float4*>(g_WhT + (size_t)s * NH * NL);
            float4* w1 = reinterpret_cast<float4*>(wqT);
            float4* w2 = reinterpret_cast<float4*>(whT);
            for (int e = t; e < NH * NL / 4; e += 256) { w1[e] = a4[e]; w2[e] = b4[e]; }
        }
        __syncthreads();

        // Phase A: acc[r][c] = sum_h tanh(wq[i0+r][h] * wh[j0+c][h])
        float acc[4][4];
        #pragma unroll
        for (int r = 0; r < 4; r++)
            #pragma unroll
            for (int c = 0; c < 4; c++) acc[r][c] = 0.f;

        #pragma unroll 2
        for (int h = 0; h < NH; h++) {
            float4 a4 = *reinterpret_cast<const float4*>(&wqT[h * NL + i0]);
            float4 b4 = *reinterpret_cast<const float4*>(&whT[h * NL + j0]);
            float av[4] = {a4.x, a4.y, a4.z, a4.w};
            float bv[4] = {b4.x, b4.y, b4.z, b4.w};
            #pragma unroll
            for (int r = 0; r < 4; r++)
                #pragma unroll
                for (int c = 0; c < 4; c++)
                    acc[r][c] += fast_tanh(av[r] * bv[c]);
        }

        // Phase B: softmax over j per row.
        float inv[4];
        #pragma unroll
        for (int r = 0; r < 4; r++) {
            float m = fmaxf(fmaxf(acc[r][0], acc[r][1]), fmaxf(acc[r][2], acc[r][3]));
            #pragma unroll
            for (int d = 1; d < 16; d <<= 1)
                m = fmaxf(m, __shfl_xor_sync(0xffffffffu, m, d));
            float e0 = fast_ex2((acc[r][0] - m) * LOG2E);
            float e1 = fast_ex2((acc[r][1] - m) * LOG2E);
            float e2 = fast_ex2((acc[r][2] - m) * LOG2E);
            float e3 = fast_ex2((acc[r][3] - m) * LOG2E);
            acc[r][0] = e0; acc[r][1] = e1; acc[r][2] = e2; acc[r][3] = e3;
            float ssum = (e0 + e1) + (e2 + e3);
            #pragma unroll
            for (int d = 1; d < 16; d <<= 1)
                ssum += __shfl_xor_sync(0xffffffffu, ssum, d);
            inv[r] = fast_rcp(ssum);
        }

        __syncthreads();  // all phase-A smem reads complete before overlay writes

        const float* hbase = g_hsT32 + (size_t)s * NL * NF;

        // Store att tf32-rounded [i][j]; concurrently stage f-chunk 0 into hsb0.
        #pragma unroll
        for (int r = 0; r < 4; r++) {
            float vh[4];
            #pragma unroll
            for (int c = 0; c < 4; c++)
                vh[c] = __uint_as_float(cvt_tf32(acc[r][c] * inv[r]));
            *reinterpret_cast<float4*>(&attH[(i0 + r) * ATS + j0]) =
                make_float4(vh[0], vh[1], vh[2], vh[3]);
        }
        #pragma unroll
        for (int e = t; e < NL * 64 / 4; e += 256) {
            int j = e >> 4;
            int f4 = (e & 15) * 4;
            *reinterpret_cast<float4*>(&hsb0[j * HSS + f4]) =
                __ldg(reinterpret_cast<const float4*>(&hbase[(size_t)j * NF + f4]));
        }
        __syncthreads();   // att + chunk 0 visible

        // Phase C: 4 f-passes; pass p computes from buf (p&1) while staging
        // pass p+1 into buf ((p+1)&1). One sync per pass.
        float* ob = out + (size_t)((q * NS + s) * NL) * NF;

        #pragma unroll
        for (int p = 0; p < 4; p++) {
            float* cur = (p & 1) ? hsb1 : hsb0;
            float* nxt = (p & 1) ? hsb0 : hsb1;

            if (p < 3) {   // stage next chunk (LDG latency hides behind compute below)
                #pragma unroll
                for (int e = t; e < NL * 64 / 4; e += 256) {
                    int j = e >> 4;
                    int f4 = (e & 15) * 4;
                    *reinterpret_cast<float4*>(&nxt[j * HSS + f4]) =
                        __ldg(reinterpret_cast<const float4*>(
                            &hbase[(size_t)j * NF + 64 * (p + 1) + f4]));
                }
            }

            float d[4][4];
            #pragma unroll
            for (int nt = 0; nt < 4; nt++)
                #pragma unroll
                for (int e = 0; e < 4; e++) d[nt][e] = 0.f;

            const float* aH = attH + (size_t)(m0 + gid) * ATS;

            #pragma unroll
            for (int k0 = 0; k0 < NL; k0 += 8) {
                unsigned ah0 = __float_as_uint(aH[k0 + tig]);
                unsigned ah1 = __float_as_uint(aH[8 * ATS + k0 + tig]);
                unsigned ah2 = __float_as_uint(aH[k0 + tig + 4]);
                unsigned ah3 = __float_as_uint(aH[8 * ATS + k0 + tig + 4]);
                const float* hr0 = cur + (size_t)(k0 + tig) * HSS + nw + gid;
                const float* hr1 = cur + (size_t)(k0 + tig + 4) * HSS + nw + gid;
                #pragma unroll
                for (int nt = 0; nt < 4; nt++) {
                    unsigned b0 = __float_as_uint(hr0[8 * nt]);
                    unsigned b1 = __float_as_uint(hr1[8 * nt]);
                    mma_tf32(d[nt], ah0, ah1, ah2, ah3, b0, b1);
                }
            }

            #pragma unroll
            for (int nt = 0; nt < 4; nt++) {
                int col = 64 * p + nw + 8 * nt + 2 * tig;
                *reinterpret_cast<float2*>(&ob[(size_t)(m0 + gid) * NF + col]) =
                    make_float2(d[nt][0], d[nt][1]);
                *reinterpret_cast<float2*>(&ob[(size_t)(m0 + gid + 8) * NF + col]) =
                    make_float2(d[nt][2], d[nt][3]);
            }

            if (p == 3 && t == 0)   // prefetch next ticket; ATOMG hides in pass 3
                tslot[0] = __uint_as_float(atomicAdd(&g_ticket, 1u));
            __syncthreads();   // staging (p+1) visible; cur free for reuse; tslot published
        }
    }
}

extern "C" void kernel_launch(void* const* d_in, const int* in_sizes, int n_in,
                              void* d_out, int out_size) {
    const float* qs = (const float*)d_in[0];
    const float* hs = (const float*)d_in[1];
    const float* W  = (const float*)d_in[2];
    const float* b  = (const float*)d_in[3];
    float* out = (float*)d_out;

    const int smem_attn = 13572 * (int)sizeof(float);  // 54288 B -> occ 4
    cudaFuncSetAttribute(k_attn, cudaFuncAttributeMaxDynamicSharedMemorySize, smem_attn);

    k_project<<<(NQ + NS) * 4, 256>>>(qs, hs, W, b);
    k_attn<<<148 * 4, 256, smem_attn>>>(out);
}